// round 1
// baseline (speedup 1.0000x reference)
#include <cuda_runtime.h>
#include <math.h>

// Problem constants
#define BSZ  4096            // batch rows (features)
#define NCLS 1000            // class centers
#define BO   4096            // OOD rows
#define NCOL (BSZ+NCLS+BO)   // 9192 total anchor columns
#define NPAD 9216            // padded to multiple of TN
#define DD   512             // feature dim
#define INV_T 10.0f          // 1/temperature
#define SHIFT 10.0f          // fixed logit shift (logits <= 10 since unit vectors)

// Tiling
#define TM 64
#define TN 64
#define BK 16
#define NS 6                               // column splits
#define COLT (NPAD/TN)                     // 144 column tiles
#define TILES_PER_S (COLT/NS)              // 24 tiles per split

// ---------------- device scratch (static; no allocations) ----------------
__device__ int   g_cntAll[NCLS];           // per-class count over targets_all_class
__device__ int   g_cntB[NCLS];             // per-class count over batch targets only
__device__ int   g_lbl[NPAD];              // column label for mask (-1 pad, NCLS for ood)
__device__ float g_inv0[NPAD];             // 1/cnt           (mask=0 case; 0 for pad)
__device__ float g_inv1[NPAD];             // 1/(cnt-1)       (mask=1 case)
__device__ const float* g_ptr[NPAD];       // column feature row pointer (null for pad)
__device__ float g_S1 [NS][BSZ];           // partial sum of mask*raw_logit
__device__ float g_den[NS][BSZ];           // partial sum of exp(raw-10)/w

// ---------------- setup kernels ----------------
__global__ void k_zero() {
    int i = blockIdx.x * blockDim.x + threadIdx.x;
    if (i < NCLS) { g_cntAll[i] = 0; g_cntB[i] = 0; }
}

__global__ void k_hist(const int* __restrict__ targets, const int* __restrict__ pseudo) {
    int i = blockIdx.x * blockDim.x + threadIdx.x;
    if (i < BSZ) {
        int t = targets[i];
        atomicAdd(&g_cntB[t], 1);
        atomicAdd(&g_cntAll[t], 1);
    }
    if (i < NCLS) atomicAdd(&g_cntAll[i], 1);   // each class center adds 1
    if (i < BO)   atomicAdd(&g_cntAll[pseudo[i]], 1);
}

__global__ void k_cols(const float* __restrict__ centers, const float* __restrict__ feats,
                       const int* __restrict__ targets,  const float* __restrict__ food,
                       const int* __restrict__ pseudo) {
    int j = blockIdx.x * blockDim.x + threadIdx.x;
    if (j >= NPAD) return;
    int lbl, cls; const float* p;
    if (j < BSZ)            { lbl = targets[j];        cls = lbl;                 p = feats   + (size_t)j * DD; }
    else if (j < BSZ+NCLS)  { lbl = j - BSZ;           cls = lbl;                 p = centers + (size_t)(j-BSZ) * DD; }
    else if (j < NCOL)      { lbl = NCLS;              cls = pseudo[j-BSZ-NCLS];  p = food    + (size_t)(j-BSZ-NCLS) * DD; }
    else { g_lbl[j] = -1; g_inv0[j] = 0.f; g_inv1[j] = 0.f; g_ptr[j] = nullptr; return; }
    float w0 = (float)g_cntAll[cls];
    g_lbl[j]  = lbl;
    g_inv0[j] = 1.0f / w0;
    g_inv1[j] = (w0 > 1.5f) ? 1.0f / (w0 - 1.0f) : 0.f;  // only read when mask=1 (then w0>=2)
    g_ptr[j]  = p;
}

// ---------------- main fused GEMM + weighted-LSE partials ----------------
__global__ __launch_bounds__(256, 2)
void k_main(const float* __restrict__ feats, const int* __restrict__ targets) {
    __shared__ float As[BK][TM];
    __shared__ float Bs[BK][TN];
    __shared__ const float* ptrS[TN];
    __shared__ int   lblS[TN];
    __shared__ float i0S[TN];
    __shared__ float i1S[TN];
    __shared__ float red[TM][17];

    const int tid = threadIdx.x;
    const int tx = tid & 15;          // 0..15 -> 4 cols each
    const int ty = tid >> 4;          // 0..15 -> 4 rows each
    const int rowBase = blockIdx.x * TM;
    const int split   = blockIdx.y;
    const int rg0 = rowBase + ty * 4;

    int myLbl[4];
    #pragma unroll
    for (int i = 0; i < 4; i++) myLbl[i] = targets[rg0 + i];

    // loader mapping: one float4 per thread per operand per k-step
    const int la_m = tid >> 2;          // row/col index 0..63
    const int la_k = (tid & 3) * 4;     // k sub-offset 0,4,8,12
    const float* aRow = feats + (size_t)(rowBase + la_m) * DD;

    float den[4] = {0.f, 0.f, 0.f, 0.f};
    float s1 [4] = {0.f, 0.f, 0.f, 0.f};

    for (int t = 0; t < TILES_PER_S; ++t) {
        const int colBase = (split * TILES_PER_S + t) * TN;

        __syncthreads();                       // previous tile's epilogue done reading meta
        if (tid < TN) {
            int jg = colBase + tid;
            ptrS[tid] = g_ptr[jg];
            lblS[tid] = g_lbl[jg];
            i0S[tid]  = g_inv0[jg];
            i1S[tid]  = g_inv1[jg];
        }

        float acc[4][4];
        #pragma unroll
        for (int a = 0; a < 4; a++)
            #pragma unroll
            for (int b = 0; b < 4; b++) acc[a][b] = 0.f;

        #pragma unroll 1
        for (int kb = 0; kb < DD; kb += BK) {
            __syncthreads();                   // smem free + (kb==0) meta visible
            // A tile: [TM rows][BK k], transpose-store
            float4 av = *(const float4*)(aRow + kb + la_k);
            As[la_k+0][la_m] = av.x; As[la_k+1][la_m] = av.y;
            As[la_k+2][la_m] = av.z; As[la_k+3][la_m] = av.w;
            // B tile: column la_m of features_all
            const float* bp = ptrS[la_m];
            float4 bv = bp ? *(const float4*)(bp + kb + la_k) : make_float4(0.f,0.f,0.f,0.f);
            Bs[la_k+0][la_m] = bv.x; Bs[la_k+1][la_m] = bv.y;
            Bs[la_k+2][la_m] = bv.z; Bs[la_k+3][la_m] = bv.w;
            __syncthreads();

            #pragma unroll
            for (int k = 0; k < BK; k++) {
                float4 a = *(const float4*)&As[k][ty * 4];
                float4 b = *(const float4*)&Bs[k][tx * 4];
                acc[0][0] += a.x*b.x; acc[0][1] += a.x*b.y; acc[0][2] += a.x*b.z; acc[0][3] += a.x*b.w;
                acc[1][0] += a.y*b.x; acc[1][1] += a.y*b.y; acc[1][2] += a.y*b.z; acc[1][3] += a.y*b.w;
                acc[2][0] += a.z*b.x; acc[2][1] += a.z*b.y; acc[2][2] += a.z*b.z; acc[2][3] += a.z*b.w;
                acc[3][0] += a.w*b.x; acc[3][1] += a.w*b.y; acc[3][2] += a.w*b.z; acc[3][3] += a.w*b.w;
            }
        }

        // epilogue: weighted exp-sum + positive-logit sum (pad cols: lbl=-1, inv0=0)
        #pragma unroll
        for (int jj = 0; jj < 4; jj++) {
            const int jg = colBase + tx * 4 + jj;
            const int   cl = lblS[tx * 4 + jj];
            const float v0 = i0S[tx * 4 + jj];
            const float v1 = i1S[tx * 4 + jj];
            #pragma unroll
            for (int ii = 0; ii < 4; ii++) {
                const int rg = rg0 + ii;
                float logit = acc[ii][jj] * INV_T;
                float p = __expf(logit - SHIFT);
                bool self = (jg == rg);
                bool m = (cl == myLbl[ii]) && !self;
                float inv = m ? v1 : v0;
                if (!self) den[ii] += p * inv;
                if (m)     s1[ii]  += logit;
            }
        }
    }

    // cross-tx reduction (16 partials per row), unique-slot deterministic writes
    #pragma unroll
    for (int ii = 0; ii < 4; ii++) red[ty*4+ii][tx] = den[ii];
    __syncthreads();
    if (tx == 0) {
        #pragma unroll
        for (int ii = 0; ii < 4; ii++) {
            float s = 0.f;
            #pragma unroll
            for (int c = 0; c < 16; c++) s += red[ty*4+ii][c];
            g_den[split][rowBase + ty*4 + ii] = s;
        }
    }
    __syncthreads();
    #pragma unroll
    for (int ii = 0; ii < 4; ii++) red[ty*4+ii][tx] = s1[ii];
    __syncthreads();
    if (tx == 0) {
        #pragma unroll
        for (int ii = 0; ii < 4; ii++) {
            float s = 0.f;
            #pragma unroll
            for (int c = 0; c < 16; c++) s += red[ty*4+ii][c];
            g_S1[split][rowBase + ty*4 + ii] = s;
        }
    }
}

// ---------------- final scalar reduction ----------------
__global__ void k_final(const int* __restrict__ targets, float* __restrict__ out) {
    __shared__ float sred[256];
    float local = 0.f;
    for (int i = threadIdx.x; i < BSZ; i += 256) {
        float s1 = 0.f, den = 0.f;
        #pragma unroll
        for (int s = 0; s < NS; s++) { s1 += g_S1[s][i]; den += g_den[s][i]; }
        float npos = (float)g_cntB[targets[i]];   // (#batch peers - self) + center
        local += s1 / npos - SHIFT - logf(den);
    }
    sred[threadIdx.x] = local;
    __syncthreads();
    for (int o = 128; o > 0; o >>= 1) {
        if (threadIdx.x < o) sred[threadIdx.x] += sred[threadIdx.x + o];
        __syncthreads();
    }
    if (threadIdx.x == 0) out[0] = -sred[0] / (float)BSZ;
}

// ---------------- launch ----------------
extern "C" void kernel_launch(void* const* d_in, const int* in_sizes, int n_in,
                              void* d_out, int out_size) {
    const float* centers = (const float*)d_in[0];   // [1000,512]
    const float* feats   = (const float*)d_in[1];   // [4096,512]
    const int*   targets = (const int*)  d_in[2];   // [4096]
    const float* food    = (const float*)d_in[3];   // [4096,512]
    const int*   pseudo  = (const int*)  d_in[4];   // [4096]
    float* out = (float*)d_out;

    k_zero<<<4, 256>>>();
    k_hist<<<16, 256>>>(targets, pseudo);
    k_cols<<<NPAD / 256, 256>>>(centers, feats, targets, food, pseudo);
    dim3 grid(BSZ / TM, NS);
    k_main<<<grid, 256>>>(feats, targets);
    k_final<<<1, 256>>>(targets, out);
}

// round 5
// speedup vs baseline: 3.0723x; 3.0723x over previous
#include <cuda_runtime.h>
#include <cuda_bf16.h>
#include <math.h>
#include <stdint.h>

// ---------------- problem constants ----------------
#define BSZ  4096
#define NCLS 1000
#define BO   4096
#define NCOL (BSZ+NCLS+BO)    // 9192
#define NPAD 9216             // padded to 256
#define DD   512
#define INV_T 10.0f
#define SHIFT 10.0f

// ---------------- tiling ----------------
#define M_TILE 128
#define N_TILE 256
#define KCH    64                  // k-chunk: 64 bf16 = 128 B rows
#define NKC    (DD/KCH)            // 8
#define MT     (BSZ/M_TILE)        // 32
#define NT     (NPAD/N_TILE)       // 36

// smem tile offsets within one buffer
#define T_AH 0
#define T_AL 16384
#define T_BH 32768
#define T_BL 65536
#define BUF_SZ 98304               // 96 KB
#define SMEM_SZ (2*BUF_SZ)         // 192 KB

#define SWZ(x) ((x) ^ (((x)>>3)&0x70))

// ---------------- device scratch ----------------
__device__ __nv_bfloat16 g_hi[(size_t)NPAD*DD];
__device__ __nv_bfloat16 g_lo[(size_t)NPAD*DD];
__device__ int   g_cntAll[NCLS];
__device__ int   g_cntB[NCLS];
__device__ int   g_lbl[NPAD];
__device__ float g_inv0[NPAD];
__device__ float g_inv1[NPAD];
__device__ float g_S1 [NT][BSZ];
__device__ float g_den[NT][BSZ];

// ---------------- ptx helpers (base-PTX only: sm_80-era ops) ----------------
__device__ __forceinline__ uint32_t s2u(const void* p) {
    uint32_t a;
    asm("{ .reg .u64 t; cvta.to.shared.u64 t, %1; cvt.u32.u64 %0, t; }" : "=r"(a) : "l"(p));
    return a;
}
__device__ __forceinline__ void ldsm4(uint32_t* r, uint32_t addr) {
    asm volatile("ldmatrix.sync.aligned.m8n8.x4.shared.b16 {%0,%1,%2,%3}, [%4];"
        : "=r"(r[0]), "=r"(r[1]), "=r"(r[2]), "=r"(r[3]) : "r"(addr));
}
__device__ __forceinline__ void mma16816(float* c, const uint32_t* a, uint32_t b0, uint32_t b1) {
    asm volatile("mma.sync.aligned.m16n8k16.row.col.f32.bf16.bf16.f32 "
        "{%0,%1,%2,%3}, {%4,%5,%6,%7}, {%8,%9}, {%0,%1,%2,%3};"
        : "+f"(c[0]), "+f"(c[1]), "+f"(c[2]), "+f"(c[3])
        : "r"(a[0]), "r"(a[1]), "r"(a[2]), "r"(a[3]), "r"(b0), "r"(b1));
}
__device__ __forceinline__ void cp16(uint32_t dst, const void* src) {
    asm volatile("cp.async.cg.shared.global [%0], [%1], 16;" :: "r"(dst), "l"(src) : "memory");
}

// ---------------- setup kernels ----------------
__global__ void k_zero() {
    int i = blockIdx.x * blockDim.x + threadIdx.x;
    if (i < NCLS) { g_cntAll[i] = 0; g_cntB[i] = 0; }
}

__global__ void k_hist(const int* __restrict__ targets, const int* __restrict__ pseudo) {
    int i = blockIdx.x * blockDim.x + threadIdx.x;
    if (i < BSZ) {
        int t = targets[i];
        atomicAdd(&g_cntB[t], 1);
        atomicAdd(&g_cntAll[t], 1);
    }
    if (i < NCLS) atomicAdd(&g_cntAll[i], 1);
    if (i < BO)   atomicAdd(&g_cntAll[pseudo[i]], 1);
}

__global__ void k_cols(const int* __restrict__ targets, const int* __restrict__ pseudo) {
    int j = blockIdx.x * blockDim.x + threadIdx.x;
    if (j >= NPAD) return;
    int lbl, cls;
    if (j < BSZ)           { lbl = targets[j];  cls = lbl; }
    else if (j < BSZ+NCLS) { lbl = j - BSZ;     cls = lbl; }
    else if (j < NCOL)     { lbl = NCLS;        cls = pseudo[j-BSZ-NCLS]; }
    else { g_lbl[j] = -1; g_inv0[j] = 0.f; g_inv1[j] = 0.f; return; }
    float w0 = (float)g_cntAll[cls];
    g_lbl[j]  = lbl;
    g_inv0[j] = 1.0f / w0;
    g_inv1[j] = (w0 > 1.5f) ? 1.0f / (w0 - 1.0f) : 0.f;
}

// hi/lo bf16 split of features_all (pad rows -> 0)
__global__ void k_conv(const float* __restrict__ centers, const float* __restrict__ feats,
                       const float* __restrict__ food) {
    int idx = blockIdx.x * blockDim.x + threadIdx.x;
    if (idx >= NPAD * DD) return;
    int j = idx >> 9;
    int k = idx & 511;
    float f;
    if (j < BSZ)            f = feats  [((size_t)j << 9) + k];
    else if (j < BSZ+NCLS)  f = centers[((size_t)(j-BSZ) << 9) + k];
    else if (j < NCOL)      f = food   [((size_t)(j-BSZ-NCLS) << 9) + k];
    else                    f = 0.f;
    __nv_bfloat16 hb = __float2bfloat16(f);
    g_hi[idx] = hb;
    g_lo[idx] = __float2bfloat16(f - __bfloat162float(hb));
}

// ---------------- main HMMA GEMM + fused epilogue ----------------
__global__ __launch_bounds__(256, 1)
void k_main(const int* __restrict__ targets) {
    extern __shared__ __align__(1024) char sm[];
    const uint32_t sb = s2u(sm);
    const int tid  = threadIdx.x;
    const int wid  = tid >> 5;
    const int lane = tid & 31;
    const int warpM = wid & 1;       // 2 row groups of 64
    const int warpN = wid >> 1;      // 4 col groups of 64
    const int rowBase = blockIdx.x * M_TILE;
    const int colBase = blockIdx.y * N_TILE;

    float acc[4][8][4];
    #pragma unroll
    for (int a = 0; a < 4; a++)
        #pragma unroll
        for (int b = 0; b < 8; b++)
            #pragma unroll
            for (int d = 0; d < 4; d++) acc[a][b][d] = 0.f;

    // ---- cp.async loader for one k-chunk ----
    // 768 tile rows x 8 segments of 16B = 6144 ops, 24 per thread
    auto load_chunk = [&](int c) {
        const uint32_t bo = (uint32_t)(c & 1) * BUF_SZ;
        const int kb = c * KCH;
        #pragma unroll
        for (int i = 0; i < 24; i++) {
            int q   = tid + i * 256;
            int seg = q & 7;
            int u   = q >> 3;
            const __nv_bfloat16* src; uint32_t tOff; int lr, gr;
            if (u < 128)      { lr = u;       gr = rowBase + lr; src = g_hi; tOff = T_AH; }
            else if (u < 256) { lr = u - 128; gr = rowBase + lr; src = g_lo; tOff = T_AL; }
            else if (u < 512) { lr = u - 256; gr = colBase + lr; src = g_hi; tOff = T_BH; }
            else              { lr = u - 512; gr = colBase + lr; src = g_lo; tOff = T_BL; }
            uint32_t off = (uint32_t)lr * 128 + (uint32_t)seg * 16;
            cp16(sb + bo + tOff + SWZ(off), src + (((size_t)gr) << 9) + kb + seg * 8);
        }
        asm volatile("cp.async.commit_group;" ::: "memory");
    };

    const int lr15 = lane & 15;
    const int lk   = (lane >> 4) * 16;

    load_chunk(0);

    for (int c = 0; c < NKC; ++c) {
        if (c + 1 < NKC) {
            load_chunk(c + 1);
            asm volatile("cp.async.wait_group 1;" ::: "memory");
        } else {
            asm volatile("cp.async.wait_group 0;" ::: "memory");
        }
        __syncthreads();

        const uint32_t bo = (uint32_t)(c & 1) * BUF_SZ;
        #pragma unroll
        for (int ks = 0; ks < 4; ++ks) {
            uint32_t aH[4][4], aL[4][4];
            #pragma unroll
            for (int mb = 0; mb < 4; ++mb) {
                uint32_t ro = (uint32_t)(warpM * 64 + mb * 16 + lr15) * 128 + ks * 32 + lk;
                ldsm4(aH[mb], sb + bo + T_AH + SWZ(ro));
                ldsm4(aL[mb], sb + bo + T_AL + SWZ(ro));
            }
            #pragma unroll
            for (int ns = 0; ns < 2; ++ns) {
                uint32_t bH[2][4], bL[2][4];
                #pragma unroll
                for (int g = 0; g < 2; ++g) {
                    uint32_t co = (uint32_t)(warpN * 64 + ns * 32 + g * 16 + lr15) * 128 + ks * 32 + lk;
                    ldsm4(bH[g], sb + bo + T_BH + SWZ(co));
                    ldsm4(bL[g], sb + bo + T_BL + SWZ(co));
                }
                #pragma unroll
                for (int mb = 0; mb < 4; ++mb)
                    #pragma unroll
                    for (int g = 0; g < 2; ++g)
                        #pragma unroll
                        for (int h = 0; h < 2; ++h) {
                            float* cc = acc[mb][ns * 4 + g * 2 + h];
                            mma16816(cc, aH[mb], bH[g][h], bH[g][h + 2]);  // hi*hi
                            mma16816(cc, aH[mb], bL[g][h], bL[g][h + 2]);  // hi*lo
                            mma16816(cc, aL[mb], bH[g][h], bH[g][h + 2]);  // lo*hi
                        }
            }
        }
        __syncthreads();
    }

    // ---- epilogue: weighted exp-sum + positive-logit sum, all in registers ----
    const int groupID = lane >> 2;
    const int tig     = lane & 3;

    int rows[8], myL[8];
    #pragma unroll
    for (int mb = 0; mb < 4; ++mb)
        #pragma unroll
        for (int rh = 0; rh < 2; ++rh) {
            int r = rowBase + warpM * 64 + mb * 16 + groupID + rh * 8;
            rows[mb * 2 + rh] = r;
            myL [mb * 2 + rh] = targets[r];
        }

    float den[8], s1[8];
    #pragma unroll
    for (int r = 0; r < 8; ++r) { den[r] = 0.f; s1[r] = 0.f; }

    #pragma unroll
    for (int nb = 0; nb < 8; ++nb) {
        #pragma unroll
        for (int j2 = 0; j2 < 2; ++j2) {
            const int col = colBase + warpN * 64 + nb * 8 + tig * 2 + j2;
            const int   cl = g_lbl[col];
            const float v0 = g_inv0[col];
            const float v1 = g_inv1[col];
            #pragma unroll
            for (int mb = 0; mb < 4; ++mb)
                #pragma unroll
                for (int rh = 0; rh < 2; ++rh) {
                    const int idx = mb * 2 + rh;
                    float logit = acc[mb][nb][rh * 2 + j2] * INV_T;
                    float p = __expf(logit - SHIFT);
                    bool self = (col == rows[idx]);
                    bool m = (cl == myL[idx]) && !self;
                    if (!self) den[idx] += p * (m ? v1 : v0);
                    if (m)     s1[idx]  += logit;
                }
        }
    }

    // reduce across the 4 lanes (tig) that share the same rows
    #pragma unroll
    for (int r = 0; r < 8; ++r) {
        den[r] += __shfl_xor_sync(0xFFFFFFFFu, den[r], 1);
        den[r] += __shfl_xor_sync(0xFFFFFFFFu, den[r], 2);
        s1[r]  += __shfl_xor_sync(0xFFFFFFFFu, s1[r],  1);
        s1[r]  += __shfl_xor_sync(0xFFFFFFFFu, s1[r],  2);
    }

    // cross-warpN combine via smem (aliases GEMM buffers; synced above)
    float* sden = (float*)sm;            // [128][4]
    float* ss1  = (float*)(sm + 2048);   // [128][4]
    if (tig == 0) {
        #pragma unroll
        for (int mb = 0; mb < 4; ++mb)
            #pragma unroll
            for (int rh = 0; rh < 2; ++rh) {
                int rl = warpM * 64 + mb * 16 + groupID + rh * 8;
                sden[rl * 4 + warpN] = den[mb * 2 + rh];
                ss1 [rl * 4 + warpN] = s1 [mb * 2 + rh];
            }
    }
    __syncthreads();
    if (tid < 128) {
        float d = sden[tid*4] + sden[tid*4+1] + sden[tid*4+2] + sden[tid*4+3];
        float s = ss1 [tid*4] + ss1 [tid*4+1] + ss1 [tid*4+2] + ss1 [tid*4+3];
        g_den[blockIdx.y][rowBase + tid] = d;
        g_S1 [blockIdx.y][rowBase + tid] = s;
    }
}

// ---------------- final scalar reduction ----------------
__global__ void k_final(const int* __restrict__ targets, float* __restrict__ out) {
    __shared__ float sred[256];
    float local = 0.f;
    for (int i = threadIdx.x; i < BSZ; i += 256) {
        float s1 = 0.f, den = 0.f;
        #pragma unroll
        for (int s = 0; s < NT; ++s) { s1 += g_S1[s][i]; den += g_den[s][i]; }
        float npos = (float)g_cntB[targets[i]];
        local += s1 / npos - SHIFT - logf(den);
    }
    sred[threadIdx.x] = local;
    __syncthreads();
    for (int o = 128; o > 0; o >>= 1) {
        if (threadIdx.x < o) sred[threadIdx.x] += sred[threadIdx.x + o];
        __syncthreads();
    }
    if (threadIdx.x == 0) out[0] = -sred[0] / (float)BSZ;
}

// ---------------- launch ----------------
extern "C" void kernel_launch(void* const* d_in, const int* in_sizes, int n_in,
                              void* d_out, int out_size) {
    const float* centers = (const float*)d_in[0];
    const float* feats   = (const float*)d_in[1];
    const int*   targets = (const int*)  d_in[2];
    const float* food    = (const float*)d_in[3];
    const int*   pseudo  = (const int*)  d_in[4];
    float* out = (float*)d_out;

    cudaFuncSetAttribute(k_main, cudaFuncAttributeMaxDynamicSharedMemorySize, SMEM_SZ);

    k_zero<<<4, 256>>>();
    k_hist<<<16, 256>>>(targets, pseudo);
    k_cols<<<NPAD / 256, 256>>>(targets, pseudo);
    k_conv<<<(NPAD * DD) / 256, 256>>>(centers, feats, food);
    dim3 grid(MT, NT);
    k_main<<<grid, 256, SMEM_SZ>>>(targets);
    k_final<<<1, 256>>>(targets, out);
}

// round 9
// speedup vs baseline: 6.5284x; 2.1249x over previous
#include <cuda_runtime.h>
#include <cuda_bf16.h>
#include <math.h>
#include <stdint.h>

// ---------------- problem constants ----------------
#define BSZ  4096
#define NCLS 1000
#define BO   4096
#define NCOL (BSZ+NCLS+BO)    // 9192
#define NPAD 9216             // padded to 256
#define DD   512
#define INV_T 10.0f
#define SHIFT 10.0f

// ---------------- tiling ----------------
#define M_TILE 128
#define N_TILE 256
#define KCH    64                  // k-chunk: 64 bf16 = 128 B rows
#define NKC    (DD/KCH)            // 8
#define MT     (BSZ/M_TILE)        // 32
#define NT     (NPAD/N_TILE)       // 36

// smem: 3-stage pipeline, 64 KB per stage (A_hi 16K + A_lo 16K + B_hi 32K)
#define T_AH 0
#define T_AL 16384
#define T_BH 32768
#define BUF_SZ 65536
#define SMEM_SZ (3*BUF_SZ)         // 192 KB

#define SWZ(x) ((x) ^ (((x)>>3)&0x70))

// ---------------- device scratch ----------------
__device__ __nv_bfloat16 g_hi[(size_t)NPAD*DD];
__device__ __nv_bfloat16 g_lo[(size_t)BSZ*DD];    // lo only needed for A rows (feats)
__device__ int   g_cntAll[NCLS];
__device__ int   g_cntB[NCLS];
__device__ int   g_lbl[NPAD];
__device__ float g_inv0[NPAD];
__device__ float g_inv1[NPAD];
__device__ float g_S1 [NT][BSZ];
__device__ float g_den[NT][BSZ];

// ---------------- ptx helpers (base-PTX sm_80-era ops only) ----------------
__device__ __forceinline__ uint32_t s2u(const void* p) {
    uint32_t a;
    asm("{ .reg .u64 t; cvta.to.shared.u64 t, %1; cvt.u32.u64 %0, t; }" : "=r"(a) : "l"(p));
    return a;
}
__device__ __forceinline__ void ldsm4(uint32_t* r, uint32_t addr) {
    asm volatile("ldmatrix.sync.aligned.m8n8.x4.shared.b16 {%0,%1,%2,%3}, [%4];"
        : "=r"(r[0]), "=r"(r[1]), "=r"(r[2]), "=r"(r[3]) : "r"(addr));
}
__device__ __forceinline__ void mma16816(float* c, const uint32_t* a, uint32_t b0, uint32_t b1) {
    asm volatile("mma.sync.aligned.m16n8k16.row.col.f32.bf16.bf16.f32 "
        "{%0,%1,%2,%3}, {%4,%5,%6,%7}, {%8,%9}, {%0,%1,%2,%3};"
        : "+f"(c[0]), "+f"(c[1]), "+f"(c[2]), "+f"(c[3])
        : "r"(a[0]), "r"(a[1]), "r"(a[2]), "r"(a[3]), "r"(b0), "r"(b1));
}
__device__ __forceinline__ void cp16(uint32_t dst, const void* src) {
    asm volatile("cp.async.cg.shared.global [%0], [%1], 16;" :: "r"(dst), "l"(src) : "memory");
}

// ---------------- setup kernels ----------------
__global__ void k_zero() {
    int i = blockIdx.x * blockDim.x + threadIdx.x;
    if (i < NCLS) { g_cntAll[i] = 0; g_cntB[i] = 0; }
}

__global__ void k_hist(const int* __restrict__ targets, const int* __restrict__ pseudo) {
    int i = blockIdx.x * blockDim.x + threadIdx.x;
    if (i < BSZ) {
        int t = targets[i];
        atomicAdd(&g_cntB[t], 1);
        atomicAdd(&g_cntAll[t], 1);
    }
    if (i < NCLS) atomicAdd(&g_cntAll[i], 1);
    if (i < BO)   atomicAdd(&g_cntAll[pseudo[i]], 1);
}

__global__ void k_cols(const int* __restrict__ targets, const int* __restrict__ pseudo) {
    int j = blockIdx.x * blockDim.x + threadIdx.x;
    if (j >= NPAD) return;
    int lbl, cls;
    if (j < BSZ)           { lbl = targets[j];  cls = lbl; }
    else if (j < BSZ+NCLS) { lbl = j - BSZ;     cls = lbl; }
    else if (j < NCOL)     { lbl = NCLS;        cls = pseudo[j-BSZ-NCLS]; }
    else { g_lbl[j] = -1; g_inv0[j] = 0.f; g_inv1[j] = 0.f; return; }
    float w0 = (float)g_cntAll[cls];
    g_lbl[j]  = lbl;
    g_inv0[j] = 1.0f / w0;
    g_inv1[j] = (w0 > 1.5f) ? 1.0f / (w0 - 1.0f) : 0.f;
}

// hi/lo bf16 split; vectorized 4 floats / thread. lo only for A rows (feats).
__global__ void k_conv(const float* __restrict__ centers, const float* __restrict__ feats,
                       const float* __restrict__ food) {
    int v = blockIdx.x * blockDim.x + threadIdx.x;     // one per 4-elem group
    if (v >= NPAD * (DD/4)) return;
    int j = v >> 7;                                    // row
    int k = (v & 127) * 4;                             // col
    float4 f;
    if (j < BSZ)            f = *(const float4*)(feats   + (((size_t)j) << 9) + k);
    else if (j < BSZ+NCLS)  f = *(const float4*)(centers + (((size_t)(j-BSZ)) << 9) + k);
    else if (j < NCOL)      f = *(const float4*)(food    + (((size_t)(j-BSZ-NCLS)) << 9) + k);
    else                    f = make_float4(0.f, 0.f, 0.f, 0.f);

    __nv_bfloat162 h0 = __floats2bfloat162_rn(f.x, f.y);
    __nv_bfloat162 h1 = __floats2bfloat162_rn(f.z, f.w);
    uint2 hv = make_uint2(*(uint32_t*)&h0, *(uint32_t*)&h1);
    ((uint2*)g_hi)[v] = hv;

    if (j < BSZ) {
        __nv_bfloat162 l0 = __floats2bfloat162_rn(f.x - __bfloat162float(__low2bfloat16(h0)),
                                                  f.y - __bfloat162float(__high2bfloat16(h0)));
        __nv_bfloat162 l1 = __floats2bfloat162_rn(f.z - __bfloat162float(__low2bfloat16(h1)),
                                                  f.w - __bfloat162float(__high2bfloat16(h1)));
        uint2 lv = make_uint2(*(uint32_t*)&l0, *(uint32_t*)&l1);
        ((uint2*)g_lo)[v] = lv;
    }
}

// ---------------- main HMMA GEMM (2-pass hi/lo) + fused epilogue ----------------
__global__ __launch_bounds__(256, 1)
void k_main(const int* __restrict__ targets) {
    extern __shared__ __align__(1024) char sm[];
    const uint32_t sb = s2u(sm);
    const int tid  = threadIdx.x;
    const int wid  = tid >> 5;
    const int lane = tid & 31;
    const int warpM = wid & 1;       // 2 row groups of 64
    const int warpN = wid >> 1;      // 4 col groups of 64
    const int rowBase = blockIdx.x * M_TILE;
    const int colBase = blockIdx.y * N_TILE;

    float acc[4][8][4];
    #pragma unroll
    for (int a = 0; a < 4; a++)
        #pragma unroll
        for (int b = 0; b < 8; b++)
            #pragma unroll
            for (int d = 0; d < 4; d++) acc[a][b][d] = 0.f;

    // ---- cp.async loader for one k-chunk: 512 tile rows x 8 x 16B = 4096 ops ----
    auto load_chunk = [&](int c) {
        const uint32_t bo = (uint32_t)(c % 3) * BUF_SZ;
        const int kb = c * KCH;
        #pragma unroll
        for (int i = 0; i < 16; i++) {
            int q   = tid + i * 256;
            int seg = q & 7;
            int u   = q >> 3;
            const __nv_bfloat16* src; uint32_t tOff; int lr, gr;
            if (u < 128)      { lr = u;       gr = rowBase + lr; src = g_hi; tOff = T_AH; }
            else if (u < 256) { lr = u - 128; gr = rowBase + lr; src = g_lo; tOff = T_AL; }
            else              { lr = u - 256; gr = colBase + lr; src = g_hi; tOff = T_BH; }
            uint32_t off = (uint32_t)lr * 128 + (uint32_t)seg * 16;
            cp16(sb + bo + tOff + SWZ(off), src + (((size_t)gr) << 9) + kb + seg * 8);
        }
        asm volatile("cp.async.commit_group;" ::: "memory");
    };

    const int lr15 = lane & 15;
    const int lk   = (lane >> 4) * 16;

    load_chunk(0);
    load_chunk(1);

    #pragma unroll 1
    for (int c = 0; c < NKC; ++c) {
        if (c + 2 < NKC) {
            load_chunk(c + 2);
            asm volatile("cp.async.wait_group 2;" ::: "memory");
        } else if (c + 1 < NKC) {
            asm volatile("cp.async.wait_group 1;" ::: "memory");
        } else {
            asm volatile("cp.async.wait_group 0;" ::: "memory");
        }
        __syncthreads();

        const uint32_t bo = (uint32_t)(c % 3) * BUF_SZ;
        #pragma unroll
        for (int ks = 0; ks < 4; ++ks) {
            uint32_t aH[4][4], aL[4][4];
            #pragma unroll
            for (int mb = 0; mb < 4; ++mb) {
                uint32_t ro = (uint32_t)(warpM * 64 + mb * 16 + lr15) * 128 + ks * 32 + lk;
                ldsm4(aH[mb], sb + bo + T_AH + SWZ(ro));
                ldsm4(aL[mb], sb + bo + T_AL + SWZ(ro));
            }
            #pragma unroll
            for (int ns = 0; ns < 2; ++ns) {
                uint32_t bH[2][4];
                #pragma unroll
                for (int g = 0; g < 2; ++g) {
                    uint32_t co = (uint32_t)(warpN * 64 + ns * 32 + g * 16 + lr15) * 128 + ks * 32 + lk;
                    ldsm4(bH[g], sb + bo + T_BH + SWZ(co));
                }
                #pragma unroll
                for (int mb = 0; mb < 4; ++mb)
                    #pragma unroll
                    for (int g = 0; g < 2; ++g)
                        #pragma unroll
                        for (int h = 0; h < 2; ++h) {
                            float* cc = acc[mb][ns * 4 + g * 2 + h];
                            mma16816(cc, aH[mb], bH[g][h], bH[g][h + 2]);  // hi*hi
                            mma16816(cc, aL[mb], bH[g][h], bH[g][h + 2]);  // lo*hi
                        }
            }
        }
        __syncthreads();
    }

    // ---- epilogue: weighted exp-sum + positive-logit sum, all in registers ----
    const int groupID = lane >> 2;
    const int tig     = lane & 3;

    int rows[8], myL[8];
    #pragma unroll
    for (int mb = 0; mb < 4; ++mb)
        #pragma unroll
        for (int rh = 0; rh < 2; ++rh) {
            int r = rowBase + warpM * 64 + mb * 16 + groupID + rh * 8;
            rows[mb * 2 + rh] = r;
            myL [mb * 2 + rh] = targets[r];
        }

    float den[8], s1[8];
    #pragma unroll
    for (int r = 0; r < 8; ++r) { den[r] = 0.f; s1[r] = 0.f; }

    #pragma unroll
    for (int nb = 0; nb < 8; ++nb) {
        #pragma unroll
        for (int j2 = 0; j2 < 2; ++j2) {
            const int col = colBase + warpN * 64 + nb * 8 + tig * 2 + j2;
            const int   cl = g_lbl[col];
            const float v0 = g_inv0[col];
            const float v1 = g_inv1[col];
            #pragma unroll
            for (int mb = 0; mb < 4; ++mb)
                #pragma unroll
                for (int rh = 0; rh < 2; ++rh) {
                    const int idx = mb * 2 + rh;
                    float logit = acc[mb][nb][rh * 2 + j2] * INV_T;
                    float p = __expf(logit - SHIFT);
                    bool self = (col == rows[idx]);
                    bool m = (cl == myL[idx]) && !self;
                    if (!self) den[idx] += p * (m ? v1 : v0);
                    if (m)     s1[idx]  += logit;
                }
        }
    }

    // reduce across the 4 lanes (tig) that share the same rows
    #pragma unroll
    for (int r = 0; r < 8; ++r) {
        den[r] += __shfl_xor_sync(0xFFFFFFFFu, den[r], 1);
        den[r] += __shfl_xor_sync(0xFFFFFFFFu, den[r], 2);
        s1[r]  += __shfl_xor_sync(0xFFFFFFFFu, s1[r],  1);
        s1[r]  += __shfl_xor_sync(0xFFFFFFFFu, s1[r],  2);
    }

    // cross-warpN combine via smem (aliases GEMM buffers; synced above)
    float* sden = (float*)sm;            // [128][4]
    float* ss1  = (float*)(sm + 2048);   // [128][4]
    if (tig == 0) {
        #pragma unroll
        for (int mb = 0; mb < 4; ++mb)
            #pragma unroll
            for (int rh = 0; rh < 2; ++rh) {
                int rl = warpM * 64 + mb * 16 + groupID + rh * 8;
                sden[rl * 4 + warpN] = den[mb * 2 + rh];
                ss1 [rl * 4 + warpN] = s1 [mb * 2 + rh];
            }
    }
    __syncthreads();
    if (tid < 128) {
        float d = sden[tid*4] + sden[tid*4+1] + sden[tid*4+2] + sden[tid*4+3];
        float s = ss1 [tid*4] + ss1 [tid*4+1] + ss1 [tid*4+2] + ss1 [tid*4+3];
        g_den[blockIdx.y][rowBase + tid] = d;
        g_S1 [blockIdx.y][rowBase + tid] = s;
    }
}

// ---------------- final scalar reduction ----------------
__global__ void k_final(const int* __restrict__ targets, float* __restrict__ out) {
    __shared__ float sred[256];
    float local = 0.f;
    for (int i = threadIdx.x; i < BSZ; i += 256) {
        float s1 = 0.f, den = 0.f;
        #pragma unroll
        for (int s = 0; s < NT; ++s) { s1 += g_S1[s][i]; den += g_den[s][i]; }
        float npos = (float)g_cntB[targets[i]];
        local += s1 / npos - SHIFT - logf(den);
    }
    sred[threadIdx.x] = local;
    __syncthreads();
    for (int o = 128; o > 0; o >>= 1) {
        if (threadIdx.x < o) sred[threadIdx.x] += sred[threadIdx.x + o];
        __syncthreads();
    }
    if (threadIdx.x == 0) out[0] = -sred[0] / (float)BSZ;
}

// ---------------- launch ----------------
extern "C" void kernel_launch(void* const* d_in, const int* in_sizes, int n_in,
                              void* d_out, int out_size) {
    const float* centers = (const float*)d_in[0];
    const float* feats   = (const float*)d_in[1];
    const int*   targets = (const int*)  d_in[2];
    const float* food    = (const float*)d_in[3];
    const int*   pseudo  = (const int*)  d_in[4];
    float* out = (float*)d_out;

    cudaFuncSetAttribute(k_main, cudaFuncAttributeMaxDynamicSharedMemorySize, SMEM_SZ);

    k_zero<<<4, 256>>>();
    k_hist<<<16, 256>>>(targets, pseudo);
    k_cols<<<NPAD / 256, 256>>>(targets, pseudo);
    k_conv<<<(NPAD * (DD/4) + 255) / 256, 256>>>(centers, feats, food);
    dim3 grid(MT, NT);
    k_main<<<grid, 256, SMEM_SZ>>>(targets);
    k_final<<<1, 256>>>(targets, out);
}

// round 10
// speedup vs baseline: 6.5782x; 1.0076x over previous
#include <cuda_runtime.h>
#include <cuda_bf16.h>
#include <math.h>
#include <stdint.h>

// ---------------- problem constants ----------------
#define BSZ  4096
#define NCLS 1000
#define BO   4096
#define NCOL (BSZ+NCLS+BO)    // 9192
#define NPAD 9216             // padded to 256
#define DD   512
#define INV_T 10.0f
#define SHIFT 10.0f

// ---------------- tiling ----------------
#define M_TILE 64
#define N_TILE 256
#define KCH    64                  // k-chunk: 64 bf16 = 128 B rows
#define NKC    (DD/KCH)            // 8
#define MT     (BSZ/M_TILE)        // 64
#define NT     (NPAD/N_TILE)       // 36

// smem: 2-stage pipeline, 48 KB per stage (A_hi 8K + A_lo 8K + B_hi 32K)
// 96 KB/CTA -> 2 CTAs per SM
#define T_AH 0
#define T_AL 8192
#define T_BH 16384
#define BUF_SZ 49152
#define SMEM_SZ (2*BUF_SZ)         // 96 KB

#define SWZ(x) ((x) ^ (((x)>>3)&0x70))

// ---------------- device scratch ----------------
__device__ __nv_bfloat16 g_hi[(size_t)NPAD*DD];
__device__ __nv_bfloat16 g_lo[(size_t)BSZ*DD];    // lo only needed for A rows (feats)
__device__ int   g_cntAll[NCLS];
__device__ int   g_cntB[NCLS];
__device__ int   g_lbl[NPAD];
__device__ float g_inv0[NPAD];
__device__ float g_inv1[NPAD];
__device__ float g_S1 [NT][BSZ];
__device__ float g_den[NT][BSZ];

// ---------------- ptx helpers (base-PTX sm_80-era ops only) ----------------
__device__ __forceinline__ uint32_t s2u(const void* p) {
    uint32_t a;
    asm("{ .reg .u64 t; cvta.to.shared.u64 t, %1; cvt.u32.u64 %0, t; }" : "=r"(a) : "l"(p));
    return a;
}
__device__ __forceinline__ void ldsm4(uint32_t* r, uint32_t addr) {
    asm volatile("ldmatrix.sync.aligned.m8n8.x4.shared.b16 {%0,%1,%2,%3}, [%4];"
        : "=r"(r[0]), "=r"(r[1]), "=r"(r[2]), "=r"(r[3]) : "r"(addr));
}
__device__ __forceinline__ void mma16816(float* c, const uint32_t* a, uint32_t b0, uint32_t b1) {
    asm volatile("mma.sync.aligned.m16n8k16.row.col.f32.bf16.bf16.f32 "
        "{%0,%1,%2,%3}, {%4,%5,%6,%7}, {%8,%9}, {%0,%1,%2,%3};"
        : "+f"(c[0]), "+f"(c[1]), "+f"(c[2]), "+f"(c[3])
        : "r"(a[0]), "r"(a[1]), "r"(a[2]), "r"(a[3]), "r"(b0), "r"(b1));
}
__device__ __forceinline__ void cp16(uint32_t dst, const void* src) {
    asm volatile("cp.async.cg.shared.global [%0], [%1], 16;" :: "r"(dst), "l"(src) : "memory");
}

// ---------------- setup kernels ----------------
__global__ void k_zero() {
    int i = blockIdx.x * blockDim.x + threadIdx.x;
    if (i < NCLS) { g_cntAll[i] = 0; g_cntB[i] = 0; }
}

__global__ void k_hist(const int* __restrict__ targets, const int* __restrict__ pseudo) {
    int i = blockIdx.x * blockDim.x + threadIdx.x;
    if (i < BSZ) {
        int t = targets[i];
        atomicAdd(&g_cntB[t], 1);
        atomicAdd(&g_cntAll[t], 1);
    }
    if (i < NCLS) atomicAdd(&g_cntAll[i], 1);
    if (i < BO)   atomicAdd(&g_cntAll[pseudo[i]], 1);
}

__global__ void k_cols(const int* __restrict__ targets, const int* __restrict__ pseudo) {
    int j = blockIdx.x * blockDim.x + threadIdx.x;
    if (j >= NPAD) return;
    int lbl, cls;
    if (j < BSZ)           { lbl = targets[j];  cls = lbl; }
    else if (j < BSZ+NCLS) { lbl = j - BSZ;     cls = lbl; }
    else if (j < NCOL)     { lbl = NCLS;        cls = pseudo[j-BSZ-NCLS]; }
    else { g_lbl[j] = -1; g_inv0[j] = 0.f; g_inv1[j] = 0.f; return; }
    float w0 = (float)g_cntAll[cls];
    g_lbl[j]  = lbl;
    g_inv0[j] = 1.0f / w0;
    g_inv1[j] = (w0 > 1.5f) ? 1.0f / (w0 - 1.0f) : 0.f;
}

// hi/lo bf16 split; vectorized 4 floats / thread. lo only for A rows (feats).
__global__ void k_conv(const float* __restrict__ centers, const float* __restrict__ feats,
                       const float* __restrict__ food) {
    int v = blockIdx.x * blockDim.x + threadIdx.x;     // one per 4-elem group
    if (v >= NPAD * (DD/4)) return;
    int j = v >> 7;                                    // row
    int k = (v & 127) * 4;                             // col
    float4 f;
    if (j < BSZ)            f = *(const float4*)(feats   + (((size_t)j) << 9) + k);
    else if (j < BSZ+NCLS)  f = *(const float4*)(centers + (((size_t)(j-BSZ)) << 9) + k);
    else if (j < NCOL)      f = *(const float4*)(food    + (((size_t)(j-BSZ-NCLS)) << 9) + k);
    else                    f = make_float4(0.f, 0.f, 0.f, 0.f);

    __nv_bfloat162 h0 = __floats2bfloat162_rn(f.x, f.y);
    __nv_bfloat162 h1 = __floats2bfloat162_rn(f.z, f.w);
    uint2 hv = make_uint2(*(uint32_t*)&h0, *(uint32_t*)&h1);
    ((uint2*)g_hi)[v] = hv;

    if (j < BSZ) {
        __nv_bfloat162 l0 = __floats2bfloat162_rn(f.x - __bfloat162float(__low2bfloat16(h0)),
                                                  f.y - __bfloat162float(__high2bfloat16(h0)));
        __nv_bfloat162 l1 = __floats2bfloat162_rn(f.z - __bfloat162float(__low2bfloat16(h1)),
                                                  f.w - __bfloat162float(__high2bfloat16(h1)));
        uint2 lv = make_uint2(*(uint32_t*)&l0, *(uint32_t*)&l1);
        ((uint2*)g_lo)[v] = lv;
    }
}

// ---------------- main HMMA GEMM (2-pass hi/lo) + fused epilogue ----------------
// 2 CTAs/SM: cross-CTA latency hiding for barriers & ldsm->mma dependency stalls
__global__ __launch_bounds__(256, 2)
void k_main(const int* __restrict__ targets) {
    extern __shared__ __align__(1024) char sm[];
    const uint32_t sb = s2u(sm);
    const int tid  = threadIdx.x;
    const int wid  = tid >> 5;
    const int lane = tid & 31;
    const int warpM = wid & 1;       // 2 row groups of 32
    const int warpN = wid >> 1;      // 4 col groups of 64
    const int rowBase = blockIdx.x * M_TILE;
    const int colBase = blockIdx.y * N_TILE;

    float acc[2][8][4];
    #pragma unroll
    for (int a = 0; a < 2; a++)
        #pragma unroll
        for (int b = 0; b < 8; b++)
            #pragma unroll
            for (int d = 0; d < 4; d++) acc[a][b][d] = 0.f;

    // ---- cp.async loader for one k-chunk: 384 tile rows x 8 x 16B = 3072 ops ----
    auto load_chunk = [&](int c) {
        const uint32_t bo = (uint32_t)(c & 1) * BUF_SZ;
        const int kb = c * KCH;
        #pragma unroll
        for (int i = 0; i < 12; i++) {
            int q   = tid + i * 256;
            int seg = q & 7;
            int u   = q >> 3;
            const __nv_bfloat16* src; uint32_t tOff; int lr, gr;
            if (u < 64)       { lr = u;       gr = rowBase + lr; src = g_hi; tOff = T_AH; }
            else if (u < 128) { lr = u - 64;  gr = rowBase + lr; src = g_lo; tOff = T_AL; }
            else              { lr = u - 128; gr = colBase + lr; src = g_hi; tOff = T_BH; }
            uint32_t off = (uint32_t)lr * 128 + (uint32_t)seg * 16;
            cp16(sb + bo + tOff + SWZ(off), src + (((size_t)gr) << 9) + kb + seg * 8);
        }
        asm volatile("cp.async.commit_group;" ::: "memory");
    };

    const int lr15 = lane & 15;
    const int lk   = (lane >> 4) * 16;

    load_chunk(0);

    #pragma unroll 1
    for (int c = 0; c < NKC; ++c) {
        if (c + 1 < NKC) {
            load_chunk(c + 1);
            asm volatile("cp.async.wait_group 1;" ::: "memory");
        } else {
            asm volatile("cp.async.wait_group 0;" ::: "memory");
        }
        __syncthreads();

        const uint32_t bo = (uint32_t)(c & 1) * BUF_SZ;
        #pragma unroll
        for (int ks = 0; ks < 4; ++ks) {
            uint32_t aH[2][4], aL[2][4];
            #pragma unroll
            for (int mb = 0; mb < 2; ++mb) {
                uint32_t ro = (uint32_t)(warpM * 32 + mb * 16 + lr15) * 128 + ks * 32 + lk;
                ldsm4(aH[mb], sb + bo + T_AH + SWZ(ro));
                ldsm4(aL[mb], sb + bo + T_AL + SWZ(ro));
            }
            #pragma unroll
            for (int ns = 0; ns < 2; ++ns) {
                uint32_t bH[2][4];
                #pragma unroll
                for (int g = 0; g < 2; ++g) {
                    uint32_t co = (uint32_t)(warpN * 64 + ns * 32 + g * 16 + lr15) * 128 + ks * 32 + lk;
                    ldsm4(bH[g], sb + bo + T_BH + SWZ(co));
                }
                #pragma unroll
                for (int mb = 0; mb < 2; ++mb)
                    #pragma unroll
                    for (int g = 0; g < 2; ++g)
                        #pragma unroll
                        for (int h = 0; h < 2; ++h) {
                            float* cc = acc[mb][ns * 4 + g * 2 + h];
                            mma16816(cc, aH[mb], bH[g][h], bH[g][h + 2]);  // hi*hi
                            mma16816(cc, aL[mb], bH[g][h], bH[g][h + 2]);  // lo*hi
                        }
            }
        }
        __syncthreads();
    }

    // ---- epilogue: weighted exp-sum + positive-logit sum, all in registers ----
    const int groupID = lane >> 2;
    const int tig     = lane & 3;

    int rows[4], myL[4];
    #pragma unroll
    for (int mb = 0; mb < 2; ++mb)
        #pragma unroll
        for (int rh = 0; rh < 2; ++rh) {
            int r = rowBase + warpM * 32 + mb * 16 + groupID + rh * 8;
            rows[mb * 2 + rh] = r;
            myL [mb * 2 + rh] = targets[r];
        }

    float den[4], s1[4];
    #pragma unroll
    for (int r = 0; r < 4; ++r) { den[r] = 0.f; s1[r] = 0.f; }

    #pragma unroll
    for (int nb = 0; nb < 8; ++nb) {
        #pragma unroll
        for (int j2 = 0; j2 < 2; ++j2) {
            const int col = colBase + warpN * 64 + nb * 8 + tig * 2 + j2;
            const int   cl = g_lbl[col];
            const float v0 = g_inv0[col];
            const float v1 = g_inv1[col];
            #pragma unroll
            for (int mb = 0; mb < 2; ++mb)
                #pragma unroll
                for (int rh = 0; rh < 2; ++rh) {
                    const int idx = mb * 2 + rh;
                    float logit = acc[mb][nb][rh * 2 + j2] * INV_T;
                    float p = __expf(logit - SHIFT);
                    bool self = (col == rows[idx]);
                    bool m = (cl == myL[idx]) && !self;
                    if (!self) den[idx] += p * (m ? v1 : v0);
                    if (m)     s1[idx]  += logit;
                }
        }
    }

    // reduce across the 4 lanes (tig) that share the same rows
    #pragma unroll
    for (int r = 0; r < 4; ++r) {
        den[r] += __shfl_xor_sync(0xFFFFFFFFu, den[r], 1);
        den[r] += __shfl_xor_sync(0xFFFFFFFFu, den[r], 2);
        s1[r]  += __shfl_xor_sync(0xFFFFFFFFu, s1[r],  1);
        s1[r]  += __shfl_xor_sync(0xFFFFFFFFu, s1[r],  2);
    }

    // cross-warpN combine via smem (aliases GEMM buffers; synced above)
    float* sden = (float*)sm;            // [64][4]
    float* ss1  = (float*)(sm + 1024);   // [64][4]
    if (tig == 0) {
        #pragma unroll
        for (int mb = 0; mb < 2; ++mb)
            #pragma unroll
            for (int rh = 0; rh < 2; ++rh) {
                int rl = warpM * 32 + mb * 16 + groupID + rh * 8;
                sden[rl * 4 + warpN] = den[mb * 2 + rh];
                ss1 [rl * 4 + warpN] = s1 [mb * 2 + rh];
            }
    }
    __syncthreads();
    if (tid < 64) {
        float d = sden[tid*4] + sden[tid*4+1] + sden[tid*4+2] + sden[tid*4+3];
        float s = ss1 [tid*4] + ss1 [tid*4+1] + ss1 [tid*4+2] + ss1 [tid*4+3];
        g_den[blockIdx.y][rowBase + tid] = d;
        g_S1 [blockIdx.y][rowBase + tid] = s;
    }
}

// ---------------- final scalar reduction ----------------
__global__ void k_final(const int* __restrict__ targets, float* __restrict__ out) {
    __shared__ float sred[256];
    float local = 0.f;
    for (int i = threadIdx.x; i < BSZ; i += 256) {
        float s1 = 0.f, den = 0.f;
        #pragma unroll
        for (int s = 0; s < NT; ++s) { s1 += g_S1[s][i]; den += g_den[s][i]; }
        float npos = (float)g_cntB[targets[i]];
        local += s1 / npos - SHIFT - logf(den);
    }
    sred[threadIdx.x] = local;
    __syncthreads();
    for (int o = 128; o > 0; o >>= 1) {
        if (threadIdx.x < o) sred[threadIdx.x] += sred[threadIdx.x + o];
        __syncthreads();
    }
    if (threadIdx.x == 0) out[0] = -sred[0] / (float)BSZ;
}

// ---------------- launch ----------------
extern "C" void kernel_launch(void* const* d_in, const int* in_sizes, int n_in,
                              void* d_out, int out_size) {
    const float* centers = (const float*)d_in[0];
    const float* feats   = (const float*)d_in[1];
    const int*   targets = (const int*)  d_in[2];
    const float* food    = (const float*)d_in[3];
    const int*   pseudo  = (const int*)  d_in[4];
    float* out = (float*)d_out;

    cudaFuncSetAttribute(k_main, cudaFuncAttributeMaxDynamicSharedMemorySize, SMEM_SZ);

    k_zero<<<4, 256>>>();
    k_hist<<<16, 256>>>(targets, pseudo);
    k_cols<<<NPAD / 256, 256>>>(targets, pseudo);
    k_conv<<<(NPAD * (DD/4) + 255) / 256, 256>>>(centers, feats, food);
    dim3 grid(MT, NT);
    k_main<<<grid, 256, SMEM_SZ>>>(targets);
    k_final<<<1, 256>>>(targets, out);
}

// round 11
// speedup vs baseline: 10.6843x; 1.6242x over previous
#include <cuda_runtime.h>
#include <cuda_fp16.h>
#include <math.h>
#include <stdint.h>

// ---------------- problem constants ----------------
#define BSZ  4096
#define NCLS 1000
#define BO   4096
#define NCOL (BSZ+NCLS+BO)    // 9192
#define NPAD 9216             // padded to 256
#define DD   512
#define INV_T 10.0f
#define SHIFT 10.0f

// ---------------- tiling ----------------
#define M_TILE 64
#define N_TILE 256
#define KCH    64                  // k-chunk: 64 fp16 = 128 B rows
#define NKC    (DD/KCH)            // 8
#define MT     (BSZ/M_TILE)        // 64
#define NT     (NPAD/N_TILE)       // 36

// smem: 2-stage pipeline, 40 KB per stage (A 8K + B 32K) -> 80 KB/CTA, 2 CTAs/SM
#define T_AH 0
#define T_BH 8192
#define BUF_SZ 40960
#define SMEM_SZ (2*BUF_SZ)         // 80 KB

#define SWZ(x) ((x) ^ (((x)>>3)&0x70))

// ---------------- device scratch ----------------
__device__ __half g_hi[(size_t)NPAD*DD];
__device__ int   g_cntAll[NCLS];
__device__ int   g_cntB[NCLS];
__device__ int   g_lbl[NPAD];
__device__ float g_inv0[NPAD];
__device__ float g_inv1[NPAD];
__device__ float g_S1 [NT][BSZ];
__device__ float g_den[NT][BSZ];

// ---------------- ptx helpers (base-PTX sm_80-era ops only) ----------------
__device__ __forceinline__ uint32_t s2u(const void* p) {
    uint32_t a;
    asm("{ .reg .u64 t; cvta.to.shared.u64 t, %1; cvt.u32.u64 %0, t; }" : "=r"(a) : "l"(p));
    return a;
}
__device__ __forceinline__ void ldsm4(uint32_t* r, uint32_t addr) {
    asm volatile("ldmatrix.sync.aligned.m8n8.x4.shared.b16 {%0,%1,%2,%3}, [%4];"
        : "=r"(r[0]), "=r"(r[1]), "=r"(r[2]), "=r"(r[3]) : "r"(addr));
}
__device__ __forceinline__ void mma16816(float* c, const uint32_t* a, uint32_t b0, uint32_t b1) {
    asm volatile("mma.sync.aligned.m16n8k16.row.col.f32.f16.f16.f32 "
        "{%0,%1,%2,%3}, {%4,%5,%6,%7}, {%8,%9}, {%0,%1,%2,%3};"
        : "+f"(c[0]), "+f"(c[1]), "+f"(c[2]), "+f"(c[3])
        : "r"(a[0]), "r"(a[1]), "r"(a[2]), "r"(a[3]), "r"(b0), "r"(b1));
}
__device__ __forceinline__ void cp16(uint32_t dst, const void* src) {
    asm volatile("cp.async.cg.shared.global [%0], [%1], 16;" :: "r"(dst), "l"(src) : "memory");
}

// ---------------- setup kernels ----------------
__global__ void k_zero() {
    int i = blockIdx.x * blockDim.x + threadIdx.x;
    if (i < NCLS) { g_cntAll[i] = 0; g_cntB[i] = 0; }
}

__global__ void k_hist(const int* __restrict__ targets, const int* __restrict__ pseudo) {
    int i = blockIdx.x * blockDim.x + threadIdx.x;
    if (i < BSZ) {
        int t = targets[i];
        atomicAdd(&g_cntB[t], 1);
        atomicAdd(&g_cntAll[t], 1);
    }
    if (i < NCLS) atomicAdd(&g_cntAll[i], 1);
    if (i < BO)   atomicAdd(&g_cntAll[pseudo[i]], 1);
}

__global__ void k_cols(const int* __restrict__ targets, const int* __restrict__ pseudo) {
    int j = blockIdx.x * blockDim.x + threadIdx.x;
    if (j >= NPAD) return;
    int lbl, cls;
    if (j < BSZ)           { lbl = targets[j];  cls = lbl; }
    else if (j < BSZ+NCLS) { lbl = j - BSZ;     cls = lbl; }
    else if (j < NCOL)     { lbl = NCLS;        cls = pseudo[j-BSZ-NCLS]; }
    else { g_lbl[j] = -1; g_inv0[j] = 0.f; g_inv1[j] = 0.f; return; }
    float w0 = (float)g_cntAll[cls];
    g_lbl[j]  = lbl;
    g_inv0[j] = 1.0f / w0;
    g_inv1[j] = (w0 > 1.5f) ? 1.0f / (w0 - 1.0f) : 0.f;
}

// fp16 conversion of features_all (pad rows -> 0); vectorized 4 floats / thread
__global__ void k_conv(const float* __restrict__ centers, const float* __restrict__ feats,
                       const float* __restrict__ food) {
    int v = blockIdx.x * blockDim.x + threadIdx.x;     // one per 4-elem group
    if (v >= NPAD * (DD/4)) return;
    int j = v >> 7;                                    // row
    int k = (v & 127) * 4;                             // col
    float4 f;
    if (j < BSZ)            f = *(const float4*)(feats   + (((size_t)j) << 9) + k);
    else if (j < BSZ+NCLS)  f = *(const float4*)(centers + (((size_t)(j-BSZ)) << 9) + k);
    else if (j < NCOL)      f = *(const float4*)(food    + (((size_t)(j-BSZ-NCLS)) << 9) + k);
    else                    f = make_float4(0.f, 0.f, 0.f, 0.f);

    __half2 h0 = __floats2half2_rn(f.x, f.y);
    __half2 h1 = __floats2half2_rn(f.z, f.w);
    ((uint2*)g_hi)[v] = make_uint2(*(uint32_t*)&h0, *(uint32_t*)&h1);
}

// ---------------- main HMMA GEMM (fp16 single-pass) + fused epilogue ----------------
__global__ __launch_bounds__(256, 2)
void k_main(const int* __restrict__ targets) {
    extern __shared__ __align__(1024) char sm[];
    const uint32_t sb = s2u(sm);
    const int tid  = threadIdx.x;
    const int wid  = tid >> 5;
    const int lane = tid & 31;
    const int warpM = wid & 1;       // 2 row groups of 32
    const int warpN = wid >> 1;      // 4 col groups of 64
    const int rowBase = blockIdx.x * M_TILE;
    const int colBase = blockIdx.y * N_TILE;

    float acc[2][8][4];
    #pragma unroll
    for (int a = 0; a < 2; a++)
        #pragma unroll
        for (int b = 0; b < 8; b++)
            #pragma unroll
            for (int d = 0; d < 4; d++) acc[a][b][d] = 0.f;

    // ---- cp.async loader for one k-chunk: 320 tile rows x 8 x 16B = 2560 ops ----
    auto load_chunk = [&](int c) {
        const uint32_t bo = (uint32_t)(c & 1) * BUF_SZ;
        const int kb = c * KCH;
        #pragma unroll
        for (int i = 0; i < 10; i++) {
            int q   = tid + i * 256;
            int seg = q & 7;
            int u   = q >> 3;
            uint32_t tOff; int lr, gr;
            if (u < 64)  { lr = u;      gr = rowBase + lr; tOff = T_AH; }
            else         { lr = u - 64; gr = colBase + lr; tOff = T_BH; }
            uint32_t off = (uint32_t)lr * 128 + (uint32_t)seg * 16;
            cp16(sb + bo + tOff + SWZ(off), g_hi + (((size_t)gr) << 9) + kb + seg * 8);
        }
        asm volatile("cp.async.commit_group;" ::: "memory");
    };

    const int lr15 = lane & 15;
    const int lk   = (lane >> 4) * 16;

    load_chunk(0);

    #pragma unroll 1
    for (int c = 0; c < NKC; ++c) {
        if (c + 1 < NKC) {
            load_chunk(c + 1);
            asm volatile("cp.async.wait_group 1;" ::: "memory");
        } else {
            asm volatile("cp.async.wait_group 0;" ::: "memory");
        }
        __syncthreads();

        const uint32_t bo = (uint32_t)(c & 1) * BUF_SZ;
        #pragma unroll
        for (int ks = 0; ks < 4; ++ks) {
            uint32_t aH[2][4];
            #pragma unroll
            for (int mb = 0; mb < 2; ++mb) {
                uint32_t ro = (uint32_t)(warpM * 32 + mb * 16 + lr15) * 128 + ks * 32 + lk;
                ldsm4(aH[mb], sb + bo + T_AH + SWZ(ro));
            }
            #pragma unroll
            for (int ns = 0; ns < 2; ++ns) {
                uint32_t bH[2][4];
                #pragma unroll
                for (int g = 0; g < 2; ++g) {
                    uint32_t co = (uint32_t)(warpN * 64 + ns * 32 + g * 16 + lr15) * 128 + ks * 32 + lk;
                    ldsm4(bH[g], sb + bo + T_BH + SWZ(co));
                }
                #pragma unroll
                for (int mb = 0; mb < 2; ++mb)
                    #pragma unroll
                    for (int g = 0; g < 2; ++g)
                        #pragma unroll
                        for (int h = 0; h < 2; ++h)
                            mma16816(acc[mb][ns * 4 + g * 2 + h], aH[mb], bH[g][h], bH[g][h + 2]);
            }
        }
        __syncthreads();
    }

    // ---- epilogue: weighted exp-sum + positive-logit sum, all in registers ----
    const int groupID = lane >> 2;
    const int tig     = lane & 3;

    int rows[4], myL[4];
    #pragma unroll
    for (int mb = 0; mb < 2; ++mb)
        #pragma unroll
        for (int rh = 0; rh < 2; ++rh) {
            int r = rowBase + warpM * 32 + mb * 16 + groupID + rh * 8;
            rows[mb * 2 + rh] = r;
            myL [mb * 2 + rh] = targets[r];
        }

    float den[4], s1[4];
    #pragma unroll
    for (int r = 0; r < 4; ++r) { den[r] = 0.f; s1[r] = 0.f; }

    #pragma unroll
    for (int nb = 0; nb < 8; ++nb) {
        #pragma unroll
        for (int j2 = 0; j2 < 2; ++j2) {
            const int col = colBase + warpN * 64 + nb * 8 + tig * 2 + j2;
            const int   cl = g_lbl[col];
            const float v0 = g_inv0[col];
            const float v1 = g_inv1[col];
            #pragma unroll
            for (int mb = 0; mb < 2; ++mb)
                #pragma unroll
                for (int rh = 0; rh < 2; ++rh) {
                    const int idx = mb * 2 + rh;
                    float logit = acc[mb][nb][rh * 2 + j2] * INV_T;
                    float p = __expf(logit - SHIFT);
                    bool self = (col == rows[idx]);
                    bool m = (cl == myL[idx]) && !self;
                    if (!self) den[idx] += p * (m ? v1 : v0);
                    if (m)     s1[idx]  += logit;
                }
        }
    }

    // reduce across the 4 lanes (tig) that share the same rows
    #pragma unroll
    for (int r = 0; r < 4; ++r) {
        den[r] += __shfl_xor_sync(0xFFFFFFFFu, den[r], 1);
        den[r] += __shfl_xor_sync(0xFFFFFFFFu, den[r], 2);
        s1[r]  += __shfl_xor_sync(0xFFFFFFFFu, s1[r],  1);
        s1[r]  += __shfl_xor_sync(0xFFFFFFFFu, s1[r],  2);
    }

    // cross-warpN combine via smem (aliases GEMM buffers; synced above)
    float* sden = (float*)sm;            // [64][4]
    float* ss1  = (float*)(sm + 1024);   // [64][4]
    if (tig == 0) {
        #pragma unroll
        for (int mb = 0; mb < 2; ++mb)
            #pragma unroll
            for (int rh = 0; rh < 2; ++rh) {
                int rl = warpM * 32 + mb * 16 + groupID + rh * 8;
                sden[rl * 4 + warpN] = den[mb * 2 + rh];
                ss1 [rl * 4 + warpN] = s1 [mb * 2 + rh];
            }
    }
    __syncthreads();
    if (tid < 64) {
        float d = sden[tid*4] + sden[tid*4+1] + sden[tid*4+2] + sden[tid*4+3];
        float s = ss1 [tid*4] + ss1 [tid*4+1] + ss1 [tid*4+2] + ss1 [tid*4+3];
        g_den[blockIdx.y][rowBase + tid] = d;
        g_S1 [blockIdx.y][rowBase + tid] = s;
    }
}

// ---------------- final scalar reduction ----------------
__global__ void k_final(const int* __restrict__ targets, float* __restrict__ out) {
    __shared__ float sred[256];
    float local = 0.f;
    for (int i = threadIdx.x; i < BSZ; i += 256) {
        float s1 = 0.f, den = 0.f;
        #pragma unroll
        for (int s = 0; s < NT; ++s) { s1 += g_S1[s][i]; den += g_den[s][i]; }
        float npos = (float)g_cntB[targets[i]];
        local += s1 / npos - SHIFT - logf(den);
    }
    sred[threadIdx.x] = local;
    __syncthreads();
    for (int o = 128; o > 0; o >>= 1) {
        if (threadIdx.x < o) sred[threadIdx.x] += sred[threadIdx.x + o];
        __syncthreads();
    }
    if (threadIdx.x == 0) out[0] = -sred[0] / (float)BSZ;
}

// ---------------- launch ----------------
extern "C" void kernel_launch(void* const* d_in, const int* in_sizes, int n_in,
                              void* d_out, int out_size) {
    const float* centers = (const float*)d_in[0];
    const float* feats   = (const float*)d_in[1];
    const int*   targets = (const int*)  d_in[2];
    const float* food    = (const float*)d_in[3];
    const int*   pseudo  = (const int*)  d_in[4];
    float* out = (float*)d_out;

    cudaFuncSetAttribute(k_main, cudaFuncAttributeMaxDynamicSharedMemorySize, SMEM_SZ);

    k_zero<<<4, 256>>>();
    k_hist<<<16, 256>>>(targets, pseudo);
    k_cols<<<NPAD / 256, 256>>>(targets, pseudo);
    k_conv<<<(NPAD * (DD/4) + 255) / 256, 256>>>(centers, feats, food);
    dim3 grid(MT, NT);
    k_main<<<grid, 256, SMEM_SZ>>>(targets);
    k_final<<<1, 256>>>(targets, out);
}

// round 12
// speedup vs baseline: 13.8763x; 1.2988x over previous
#include <cuda_runtime.h>
#include <cuda_fp16.h>
#include <math.h>
#include <stdint.h>

// ---------------- problem constants ----------------
#define BSZ  4096
#define NCLS 1000
#define BO   4096
#define NCOL (BSZ+NCLS+BO)    // 9192
#define NPAD 9216             // padded to 256
#define DD   512
#define INV_T 10.0f
#define SHIFT 10.0f

// ---------------- tiling ----------------
#define M_TILE 64
#define N_TILE 256
#define KCH    64                  // k-chunk: 64 fp16 = 128 B rows
#define NKC    (DD/KCH)            // 8
#define MT     (BSZ/M_TILE)        // 64
#define NT     (NPAD/N_TILE)       // 36

// smem: 2-stage pipeline, 40 KB per stage (A 8K + B 32K) -> 80 KB/CTA, 2 CTAs/SM
#define T_AH 0
#define T_BH 8192
#define BUF_SZ 40960
#define SMEM_SZ (2*BUF_SZ)         // 80 KB

#define SWZ(x) ((x) ^ (((x)>>3)&0x70))

// ---------------- device scratch ----------------
__device__ __half g_hi[(size_t)NPAD*DD];
__device__ int   g_cntAll[NCLS];
__device__ int   g_cntB[NCLS];
__device__ int   g_lbl[NPAD];
__device__ float g_inv0[NPAD];
__device__ float g_inv1[NPAD];
__device__ float g_S1 [NT][BSZ];
__device__ float g_den[NT][BSZ];
__device__ float g_s12 [MT][BSZ];   // mirrored (transposed) partials, slot = source row-tile bx
__device__ float g_den2[MT][BSZ];
__device__ float g_rowv[BSZ];

// ---------------- ptx helpers (base-PTX sm_80-era ops only) ----------------
__device__ __forceinline__ uint32_t s2u(const void* p) {
    uint32_t a;
    asm("{ .reg .u64 t; cvta.to.shared.u64 t, %1; cvt.u32.u64 %0, t; }" : "=r"(a) : "l"(p));
    return a;
}
__device__ __forceinline__ void ldsm4(uint32_t* r, uint32_t addr) {
    asm volatile("ldmatrix.sync.aligned.m8n8.x4.shared.b16 {%0,%1,%2,%3}, [%4];"
        : "=r"(r[0]), "=r"(r[1]), "=r"(r[2]), "=r"(r[3]) : "r"(addr));
}
__device__ __forceinline__ void mma16816(float* c, const uint32_t* a, uint32_t b0, uint32_t b1) {
    asm volatile("mma.sync.aligned.m16n8k16.row.col.f32.f16.f16.f32 "
        "{%0,%1,%2,%3}, {%4,%5,%6,%7}, {%8,%9}, {%0,%1,%2,%3};"
        : "+f"(c[0]), "+f"(c[1]), "+f"(c[2]), "+f"(c[3])
        : "r"(a[0]), "r"(a[1]), "r"(a[2]), "r"(a[3]), "r"(b0), "r"(b1));
}
__device__ __forceinline__ void cp16(uint32_t dst, const void* src) {
    asm volatile("cp.async.cg.shared.global [%0], [%1], 16;" :: "r"(dst), "l"(src) : "memory");
}

// ---------------- setup kernels ----------------
__global__ void k_zero() {
    int i = blockIdx.x * blockDim.x + threadIdx.x;
    if (i < NCLS) { g_cntAll[i] = 0; g_cntB[i] = 0; }
}

__global__ void k_hist(const int* __restrict__ targets, const int* __restrict__ pseudo) {
    int i = blockIdx.x * blockDim.x + threadIdx.x;
    if (i < BSZ) {
        int t = targets[i];
        atomicAdd(&g_cntB[t], 1);
        atomicAdd(&g_cntAll[t], 1);
    }
    if (i < NCLS) atomicAdd(&g_cntAll[i], 1);
    if (i < BO)   atomicAdd(&g_cntAll[pseudo[i]], 1);
}

__global__ void k_cols(const int* __restrict__ targets, const int* __restrict__ pseudo) {
    int j = blockIdx.x * blockDim.x + threadIdx.x;
    if (j >= NPAD) return;
    int lbl, cls;
    if (j < BSZ)           { lbl = targets[j];  cls = lbl; }
    else if (j < BSZ+NCLS) { lbl = j - BSZ;     cls = lbl; }
    else if (j < NCOL)     { lbl = NCLS;        cls = pseudo[j-BSZ-NCLS]; }
    else { g_lbl[j] = -1; g_inv0[j] = 0.f; g_inv1[j] = 0.f; return; }
    float w0 = (float)g_cntAll[cls];
    g_lbl[j]  = lbl;
    g_inv0[j] = 1.0f / w0;
    g_inv1[j] = (w0 > 1.5f) ? 1.0f / (w0 - 1.0f) : 0.f;
}

// fp16 conversion of features_all (pad rows -> 0); vectorized 4 floats / thread
__global__ void k_conv(const float* __restrict__ centers, const float* __restrict__ feats,
                       const float* __restrict__ food) {
    int v = blockIdx.x * blockDim.x + threadIdx.x;
    if (v >= NPAD * (DD/4)) return;
    int j = v >> 7;
    int k = (v & 127) * 4;
    float4 f;
    if (j < BSZ)            f = *(const float4*)(feats   + (((size_t)j) << 9) + k);
    else if (j < BSZ+NCLS)  f = *(const float4*)(centers + (((size_t)(j-BSZ)) << 9) + k);
    else if (j < NCOL)      f = *(const float4*)(food    + (((size_t)(j-BSZ-NCLS)) << 9) + k);
    else                    f = make_float4(0.f, 0.f, 0.f, 0.f);

    __half2 h0 = __floats2half2_rn(f.x, f.y);
    __half2 h1 = __floats2half2_rn(f.z, f.w);
    ((uint2*)g_hi)[v] = make_uint2(*(uint32_t*)&h0, *(uint32_t*)&h1);
}

// ---------------- main HMMA GEMM (fp16, symmetric-skip) + fused epilogue ----------------
// Tile (bx,by): rows [64bx,64bx+64), cols [256by,256by+256).
// skip  iff 4*(by+1) <= bx        (strictly-lower inside the F*F^T block)
// upper iff bx+1 <= 4*by && by<16 (strictly-upper inside F*F^T: also emit transposed sums)
__global__ __launch_bounds__(256, 2)
void k_main(const int* __restrict__ targets) {
    if (((blockIdx.y + 1) << 2) <= blockIdx.x) return;   // lower tile: mirrored elsewhere

    extern __shared__ __align__(1024) char sm[];
    const uint32_t sb = s2u(sm);
    const int tid  = threadIdx.x;
    const int wid  = tid >> 5;
    const int lane = tid & 31;
    const int warpM = wid & 1;       // 2 row groups of 32
    const int warpN = wid >> 1;      // 4 col groups of 64
    const int rowBase = blockIdx.x * M_TILE;
    const int colBase = blockIdx.y * N_TILE;
    const bool isUp = (blockIdx.x + 1 <= 4 * blockIdx.y) && (blockIdx.y < 16);

    float acc[2][8][4];
    #pragma unroll
    for (int a = 0; a < 2; a++)
        #pragma unroll
        for (int b = 0; b < 8; b++)
            #pragma unroll
            for (int d = 0; d < 4; d++) acc[a][b][d] = 0.f;

    auto load_chunk = [&](int c) {
        const uint32_t bo = (uint32_t)(c & 1) * BUF_SZ;
        const int kb = c * KCH;
        #pragma unroll
        for (int i = 0; i < 10; i++) {
            int q   = tid + i * 256;
            int seg = q & 7;
            int u   = q >> 3;
            uint32_t tOff; int lr, gr;
            if (u < 64)  { lr = u;      gr = rowBase + lr; tOff = T_AH; }
            else         { lr = u - 64; gr = colBase + lr; tOff = T_BH; }
            uint32_t off = (uint32_t)lr * 128 + (uint32_t)seg * 16;
            cp16(sb + bo + tOff + SWZ(off), g_hi + (((size_t)gr) << 9) + kb + seg * 8);
        }
        asm volatile("cp.async.commit_group;" ::: "memory");
    };

    const int lr15 = lane & 15;
    const int lk   = (lane >> 4) * 16;

    load_chunk(0);

    #pragma unroll 1
    for (int c = 0; c < NKC; ++c) {
        if (c + 1 < NKC) {
            load_chunk(c + 1);
            asm volatile("cp.async.wait_group 1;" ::: "memory");
        } else {
            asm volatile("cp.async.wait_group 0;" ::: "memory");
        }
        __syncthreads();

        const uint32_t bo = (uint32_t)(c & 1) * BUF_SZ;
        #pragma unroll
        for (int ks = 0; ks < 4; ++ks) {
            uint32_t aH[2][4];
            #pragma unroll
            for (int mb = 0; mb < 2; ++mb) {
                uint32_t ro = (uint32_t)(warpM * 32 + mb * 16 + lr15) * 128 + ks * 32 + lk;
                ldsm4(aH[mb], sb + bo + T_AH + SWZ(ro));
            }
            #pragma unroll
            for (int ns = 0; ns < 2; ++ns) {
                uint32_t bH[2][4];
                #pragma unroll
                for (int g = 0; g < 2; ++g) {
                    uint32_t co = (uint32_t)(warpN * 64 + ns * 32 + g * 16 + lr15) * 128 + ks * 32 + lk;
                    ldsm4(bH[g], sb + bo + T_BH + SWZ(co));
                }
                #pragma unroll
                for (int mb = 0; mb < 2; ++mb)
                    #pragma unroll
                    for (int g = 0; g < 2; ++g)
                        #pragma unroll
                        for (int h = 0; h < 2; ++h)
                            mma16816(acc[mb][ns * 4 + g * 2 + h], aH[mb], bH[g][h], bH[g][h + 2]);
            }
        }
        __syncthreads();
    }

    // ---- epilogue ----
    const int groupID = lane >> 2;
    const int tig     = lane & 3;

    int rows[4], myL[4];
    float rI0[4], rI1[4];
    #pragma unroll
    for (int mb = 0; mb < 2; ++mb)
        #pragma unroll
        for (int rh = 0; rh < 2; ++rh) {
            int r = rowBase + warpM * 32 + mb * 16 + groupID + rh * 8;
            int idx = mb * 2 + rh;
            rows[idx] = r;
            myL [idx] = targets[r];
            rI0 [idx] = g_inv0[r];    // row-indexed weights for mirrored contributions
            rI1 [idx] = g_inv1[r];
        }

    float den[4], s1[4];
    #pragma unroll
    for (int r = 0; r < 4; ++r) { den[r] = 0.f; s1[r] = 0.f; }
    float cden[16], cs1[16];
    #pragma unroll
    for (int k = 0; k < 16; ++k) { cden[k] = 0.f; cs1[k] = 0.f; }

    #pragma unroll
    for (int nb = 0; nb < 8; ++nb) {
        #pragma unroll
        for (int j2 = 0; j2 < 2; ++j2) {
            const int col = colBase + warpN * 64 + nb * 8 + tig * 2 + j2;
            const int   cl = g_lbl[col];
            const float v0 = g_inv0[col];
            const float v1 = g_inv1[col];
            #pragma unroll
            for (int mb = 0; mb < 2; ++mb)
                #pragma unroll
                for (int rh = 0; rh < 2; ++rh) {
                    const int idx = mb * 2 + rh;
                    float logit = acc[mb][nb][rh * 2 + j2] * INV_T;
                    float p = __expf(logit - SHIFT);
                    bool self = (col == rows[idx]);
                    bool m = (cl == myL[idx]) && !self;
                    if (!self) den[idx] += p * (m ? v1 : v0);
                    if (m)     s1[idx]  += logit;
                    if (isUp) {                       // transposed contribution to row=col
                        cden[nb*2+j2] += p * (m ? rI1[idx] : rI0[idx]);
                        if (m) cs1[nb*2+j2] += logit;
                    }
                }
        }
    }

    // row-part: reduce across tig lanes
    #pragma unroll
    for (int r = 0; r < 4; ++r) {
        den[r] += __shfl_xor_sync(0xFFFFFFFFu, den[r], 1);
        den[r] += __shfl_xor_sync(0xFFFFFFFFu, den[r], 2);
        s1[r]  += __shfl_xor_sync(0xFFFFFFFFu, s1[r],  1);
        s1[r]  += __shfl_xor_sync(0xFFFFFFFFu, s1[r],  2);
    }

    float* sden  = (float*)sm;             // [64][4]
    float* ss1   = (float*)(sm + 1024);    // [64][4]
    float* cbufD = (float*)(sm + 4096);    // [2][256]
    float* cbufS = (float*)(sm + 8192);    // [2][256]
    if (tig == 0) {
        #pragma unroll
        for (int mb = 0; mb < 2; ++mb)
            #pragma unroll
            for (int rh = 0; rh < 2; ++rh) {
                int rl = warpM * 32 + mb * 16 + groupID + rh * 8;
                sden[rl * 4 + warpN] = den[mb * 2 + rh];
                ss1 [rl * 4 + warpN] = s1 [mb * 2 + rh];
            }
    }

    // mirror-part: reduce across rows (groupID lanes), then stage per-warpM
    if (isUp) {
        #pragma unroll
        for (int k = 0; k < 16; ++k) {
            cden[k] += __shfl_xor_sync(0xFFFFFFFFu, cden[k], 4);
            cden[k] += __shfl_xor_sync(0xFFFFFFFFu, cden[k], 8);
            cden[k] += __shfl_xor_sync(0xFFFFFFFFu, cden[k], 16);
            cs1[k]  += __shfl_xor_sync(0xFFFFFFFFu, cs1[k],  4);
            cs1[k]  += __shfl_xor_sync(0xFFFFFFFFu, cs1[k],  8);
            cs1[k]  += __shfl_xor_sync(0xFFFFFFFFu, cs1[k],  16);
        }
        if (lane < 4) {   // groupID==0; tig = lane
            #pragma unroll
            for (int nb = 0; nb < 8; ++nb)
                #pragma unroll
                for (int j2 = 0; j2 < 2; ++j2) {
                    int cc = warpN * 64 + nb * 8 + lane * 2 + j2;
                    cbufD[warpM * 256 + cc] = cden[nb*2+j2];
                    cbufS[warpM * 256 + cc] = cs1 [nb*2+j2];
                }
        }
    }
    __syncthreads();

    if (tid < 64) {
        float d = sden[tid*4] + sden[tid*4+1] + sden[tid*4+2] + sden[tid*4+3];
        float s = ss1 [tid*4] + ss1 [tid*4+1] + ss1 [tid*4+2] + ss1 [tid*4+3];
        g_den[blockIdx.y][rowBase + tid] = d;
        g_S1 [blockIdx.y][rowBase + tid] = s;
    }
    if (isUp) {
        g_den2[blockIdx.x][colBase + tid] = cbufD[tid] + cbufD[256 + tid];
        g_s12 [blockIdx.x][colBase + tid] = cbufS[tid] + cbufS[256 + tid];
    }
}

// ---------------- per-row combine (parallel) ----------------
__global__ void k_rows(const int* __restrict__ targets) {
    int i = blockIdx.x * blockDim.x + threadIdx.x;
    if (i >= BSZ) return;
    const int m8 = i >> 8;                      // this row's col-tile index
    float s1 = 0.f, den = 0.f;
    for (int by = m8; by < NT; ++by) { s1 += g_S1[by][i]; den += g_den[by][i]; }
    for (int bx = 0; bx < 4*m8; ++bx) { s1 += g_s12[bx][i]; den += g_den2[bx][i]; }
    float npos = (float)g_cntB[targets[i]];
    g_rowv[i] = s1 / npos - SHIFT - logf(den);
}

// ---------------- final scalar reduction ----------------
__global__ void k_final(float* __restrict__ out) {
    __shared__ float sred[256];
    float local = 0.f;
    for (int i = threadIdx.x; i < BSZ; i += 256) local += g_rowv[i];
    sred[threadIdx.x] = local;
    __syncthreads();
    for (int o = 128; o > 0; o >>= 1) {
        if (threadIdx.x < o) sred[threadIdx.x] += sred[threadIdx.x + o];
        __syncthreads();
    }
    if (threadIdx.x == 0) out[0] = -sred[0] / (float)BSZ;
}

// ---------------- launch ----------------
extern "C" void kernel_launch(void* const* d_in, const int* in_sizes, int n_in,
                              void* d_out, int out_size) {
    const float* centers = (const float*)d_in[0];
    const float* feats   = (const float*)d_in[1];
    const int*   targets = (const int*)  d_in[2];
    const float* food    = (const float*)d_in[3];
    const int*   pseudo  = (const int*)  d_in[4];
    float* out = (float*)d_out;

    cudaFuncSetAttribute(k_main, cudaFuncAttributeMaxDynamicSharedMemorySize, SMEM_SZ);

    k_zero<<<4, 256>>>();
    k_hist<<<16, 256>>>(targets, pseudo);
    k_cols<<<NPAD / 256, 256>>>(targets, pseudo);
    k_conv<<<(NPAD * (DD/4) + 255) / 256, 256>>>(centers, feats, food);
    dim3 grid(MT, NT);
    k_main<<<grid, 256, SMEM_SZ>>>(targets);
    k_rows<<<BSZ / 256, 256>>>(targets);
    k_final<<<1, 256>>>(out);
}